// round 10
// baseline (speedup 1.0000x reference)
#include <cuda_runtime.h>
#include <cstdint>

// Problem constants
#define TT   512      // sequence length
#define EE   1024     // embedding dim
#define HDIM 512      // per-direction hidden
#define G4   2048     // 4*HDIM gate rows
#define KTAG 32       // tags
#define NEGV (-10000.0f)
#define START_TAG 30
#define STOP_TAG  31

// LSTM recurrent kernel config
#define NBD  64              // blocks per direction
#define JPB  (HDIM / NBD)    // h-indices per block = 8
#define LSTM_THREADS 256
#define SENT 0x7FC00001u     // NaN sentinel: h = sigmoid*tanh can never be NaN

// ---------------- scratch (device globals; no allocation) ----------------
__device__ float g_xw[2][TT][G4];          // input projections + biases (scan-step indexed)
__device__ float g_lstm[TT][2 * HDIM];     // concatenated [hf | hb] (time indexed)
__device__ float g_feats[TT][KTAG];        // tag scores
__device__ float g_hx[2][TT][NBD][JPB];    // per-step h exchange slots (POISONED)

// ---------------- asm helpers ----------------
__device__ __forceinline__ float4 ldg_relaxed_v4(const float4* p) {
    float4 v;
    asm volatile("ld.global.relaxed.gpu.v4.f32 {%0,%1,%2,%3}, [%4];"
                 : "=f"(v.x), "=f"(v.y), "=f"(v.z), "=f"(v.w) : "l"(p) : "memory");
    return v;
}
__device__ __forceinline__ void stg_relaxed_v4(float4* p, float4 v) {
    asm volatile("st.global.relaxed.gpu.v4.f32 [%0], {%1,%2,%3,%4};"
                 :: "l"(p), "f"(v.x), "f"(v.y), "f"(v.z), "f"(v.w) : "memory");
}
__device__ __forceinline__ bool has_sent(float4 v) {
    return (__float_as_uint(v.x) == SENT) | (__float_as_uint(v.y) == SENT) |
           (__float_as_uint(v.z) == SENT) | (__float_as_uint(v.w) == SENT);
}
// packed f32x2 FMA (sm_100+; ptxas never emits this from C++)
__device__ __forceinline__ void fma2(uint64_t& d, uint64_t a, uint64_t b) {
    asm("fma.rn.f32x2 %0, %1, %2, %0;" : "+l"(d) : "l"(a), "l"(b));
}
__device__ __forceinline__ uint64_t pack2(float x, float y) {
    uint64_t r; asm("mov.b64 %0, {%1,%2};" : "=l"(r) : "f"(x), "f"(y)); return r;
}
__device__ __forceinline__ float2 unpack2(uint64_t v) {
    float2 f; asm("mov.b64 {%0,%1}, %2;" : "=f"(f.x), "=f"(f.y) : "l"(v)); return f;
}
__device__ __forceinline__ void lds_v2_u64(uint32_t addr, uint64_t& x, uint64_t& y) {
    asm volatile("ld.shared.v2.b64 {%0,%1}, [%2];" : "=l"(x), "=l"(y) : "r"(addr));
}
// fast activations: MUFU-based, rel err ~1e-6 (safe vs argmax margins)
__device__ __forceinline__ float fast_sig(float x) {
    return __fdividef(1.f, 1.f + __expf(-x));
}
__device__ __forceinline__ float fast_tanh(float x) {
    return 1.f - __fdividef(2.f, __expf(2.f * x) + 1.f);
}
// monotone float -> unsigned key (order-preserving)
__device__ __forceinline__ unsigned fkey(float x) {
    unsigned b = __float_as_uint(x);
    return (b & 0x80000000u) ? ~b : (b | 0x80000000u);
}

// ---------------- poison the exchange slots each launch ----------------
__global__ __launch_bounds__(256) void poison_kernel() {
    // g_hx = 2*512*64*8 floats = 131072 float4
    float4* p = (float4*)g_hx;
    float4 v = make_float4(__uint_as_float(SENT), __uint_as_float(SENT),
                           __uint_as_float(SENT), __uint_as_float(SENT));
    p[blockIdx.x * 256 + threadIdx.x] = v;
}

// ---------------- Kernel A: embed-gather + input projection GEMM ---------
// 128x128 tile, 8x8 per thread, packed f32x2 FMA inner loop. (R6-verified)
__global__ __launch_bounds__(256, 1) void gemm_xw_kernel(
    const int* __restrict__ sentence,
    const float* __restrict__ embed,
    const float* __restrict__ w_ih_f, const float* __restrict__ b_ih_f,
    const float* __restrict__ b_hh_f,
    const float* __restrict__ w_ih_b, const float* __restrict__ b_ih_b,
    const float* __restrict__ b_hh_b)
{
    int dir = blockIdx.z;
    const float* W  = dir ? w_ih_b : w_ih_f;
    const float* Bi = dir ? b_ih_b : b_ih_f;
    const float* Bh = dir ? b_hh_b : b_hh_f;

    int n0 = blockIdx.x * 128;   // gate-row tile
    int m0 = blockIdx.y * 128;   // scan-step tile

    __shared__ __align__(16) float As[8][128];
    __shared__ __align__(16) float Bs[8][128];

    int tid = threadIdx.x;
    int tx = tid & 15;           // 8 output cols
    int ty = tid >> 4;           // 8 output rows
    int lrow = tid >> 1;         // load row
    int lq   = tid & 1;          // float4 within 8-wide k slab

    int sglob = m0 + lrow;                       // scan step
    int sidx  = dir ? (TT - 1 - sglob) : sglob;  // token consumed there
    const float* aptr = embed + (size_t)sentence[sidx] * EE + lq * 4;
    const float* bptr = W + (size_t)(n0 + lrow) * EE + lq * 4;

    uint64_t acc2[8][4];
#pragma unroll
    for (int i = 0; i < 8; i++)
#pragma unroll
        for (int j = 0; j < 4; j++) acc2[i][j] = 0ull;

    uint32_t bs_base = (uint32_t)__cvta_generic_to_shared(&Bs[0][tx * 8]);
    uint32_t as_base = (uint32_t)__cvta_generic_to_shared(&As[0][ty * 8]);

    float4 a_nx = *(const float4*)aptr;
    float4 b_nx = *(const float4*)bptr;

    for (int k0 = 0; k0 < EE; k0 += 8) {
        As[lq * 4 + 0][lrow] = a_nx.x; As[lq * 4 + 1][lrow] = a_nx.y;
        As[lq * 4 + 2][lrow] = a_nx.z; As[lq * 4 + 3][lrow] = a_nx.w;
        Bs[lq * 4 + 0][lrow] = b_nx.x; Bs[lq * 4 + 1][lrow] = b_nx.y;
        Bs[lq * 4 + 2][lrow] = b_nx.z; Bs[lq * 4 + 3][lrow] = b_nx.w;
        __syncthreads();

        if (k0 + 8 < EE) {
            a_nx = *(const float4*)(aptr + k0 + 8);
            b_nx = *(const float4*)(bptr + k0 + 8);
        }

#pragma unroll
        for (int k = 0; k < 8; k++) {
            uint64_t a01, a23, a45, a67;
            lds_v2_u64(as_base + k * 512,      a01, a23);
            lds_v2_u64(as_base + k * 512 + 16, a45, a67);
            uint64_t b01, b23, b45, b67;
            lds_v2_u64(bs_base + k * 512,      b01, b23);
            lds_v2_u64(bs_base + k * 512 + 16, b45, b67);
            float2 a0 = unpack2(a01), a1 = unpack2(a23);
            float2 a2 = unpack2(a45), a3 = unpack2(a67);
            float a[8] = {a0.x, a0.y, a1.x, a1.y, a2.x, a2.y, a3.x, a3.y};
#pragma unroll
            for (int i = 0; i < 8; i++) {
                uint64_t aa = pack2(a[i], a[i]);
                fma2(acc2[i][0], aa, b01);
                fma2(acc2[i][1], aa, b23);
                fma2(acc2[i][2], aa, b45);
                fma2(acc2[i][3], aa, b67);
            }
        }
        __syncthreads();
    }

    int rbase = n0 + tx * 8;
    float4 bi0 = *(const float4*)(Bi + rbase);
    float4 bi1 = *(const float4*)(Bi + rbase + 4);
    float4 bh0 = *(const float4*)(Bh + rbase);
    float4 bh1 = *(const float4*)(Bh + rbase + 4);
    float bias[8] = {bi0.x + bh0.x, bi0.y + bh0.y, bi0.z + bh0.z, bi0.w + bh0.w,
                     bi1.x + bh1.x, bi1.y + bh1.y, bi1.z + bh1.z, bi1.w + bh1.w};
#pragma unroll
    for (int i = 0; i < 8; i++) {
        int m = m0 + ty * 8 + i;
        float2 p0 = unpack2(acc2[i][0]);
        float2 p1 = unpack2(acc2[i][1]);
        float2 p2 = unpack2(acc2[i][2]);
        float2 p3 = unpack2(acc2[i][3]);
        float4 o0 = make_float4(p0.x + bias[0], p0.y + bias[1],
                                p1.x + bias[2], p1.y + bias[3]);
        float4 o1 = make_float4(p2.x + bias[4], p2.y + bias[5],
                                p3.x + bias[6], p3.y + bias[7]);
        *(float4*)&g_xw[dir][m][rbase]     = o0;
        *(float4*)&g_xw[dir][m][rbase + 4] = o1;
    }
}

// ---------------- Kernel B: persistent recurrent LSTM --------------------
// EXACT R6 layout (measured ~380us inside the 764 run): 8-thread rows,
// gbuf reduce, warp-0 parallel-lane activations, hvx bounce, writer emits
// the whole 32B payload as TWO 16B relaxed stores from ONE warp (critical:
// warp-per-j's 8 scattered 4B stores from 8 warps regressed 2x).
// Self-throttled DEPENDENT poll (pipelined poll saturates L2 — never again).
__global__ __launch_bounds__(LSTM_THREADS, 1) void lstm_kernel(
    const float* __restrict__ w_hh_f,
    const float* __restrict__ w_hh_b,
    const float* __restrict__ h0,
    const float* __restrict__ c0)
{
    __shared__ __align__(16) float hbuf[HDIM];
    __shared__ float gbuf[32];
    __shared__ __align__(16) float hvx[8];

    int bid = blockIdx.x;
    int dir = bid / NBD;
    int blk = bid % NBD;
    int j0  = blk * JPB;
    int tid = threadIdx.x;
    int lane8 = tid & 7;
    int task  = tid >> 3;        // 0..31 = gi*8 + jj
    int gi    = task >> 3;
    int jj    = task & 7;

    const float* w_hh = dir ? w_hh_b : w_hh_f;

    // Weights into registers as packed f32x2 pairs
    const float4* wrow = (const float4*)(w_hh + (size_t)(gi * HDIM + j0 + jj) * HDIM);
    uint64_t wp[32];
#pragma unroll
    for (int i = 0; i < 16; i++) {
        float4 w4 = wrow[lane8 + 8 * i];
        wp[2 * i]     = pack2(w4.x, w4.y);
        wp[2 * i + 1] = pack2(w4.z, w4.w);
    }

    float c_reg = (tid < JPB) ? c0[dir * HDIM + j0 + tid] : 0.f;

    int pw = tid >> 1;           // writer block this thread tracks (tid<128)
    int pq = tid & 1;            // which 16B chunk of that writer's payload
    const float* xwbase = &g_xw[dir][0][gi * HDIM + j0 + jj];
    uint32_t h_base = (uint32_t)__cvta_generic_to_shared(&hbuf[0]) + lane8 * 16;

    for (int s = 0; s < TT; s++) {
        int t = dir ? (TT - 1 - s) : s;

        // prefetch xw before the spin so its latency hides under the poll
        float xwv = 0.f;
        if (lane8 == 0) xwv = __ldcg(xwbase + (size_t)s * G4);

        if (s == 0) {
            if (tid < 128)
                ((float4*)hbuf)[tid] = ((const float4*)(h0 + dir * HDIM))[tid];
        } else if (tid < 128) {
            const float4* src = (const float4*)&g_hx[dir][s - 1][pw][0] + pq;
            float4 hv4;
            do { hv4 = ldg_relaxed_v4(src); } while (has_sent(hv4));
            *((float4*)&hbuf[pw * 8] + pq) = hv4;
        }
        __syncthreads();

        // h . w_row with packed f32x2 FMA, 4 independent chains
        uint64_t aA = 0ull, aB = 0ull, aC = 0ull, aD = 0ull;
#pragma unroll
        for (int i = 0; i < 16; i += 2) {
            uint64_t h0p, h1p, h2p, h3p;
            lds_v2_u64(h_base + i * 128, h0p, h1p);
            lds_v2_u64(h_base + i * 128 + 128, h2p, h3p);
            fma2(aA, wp[2 * i],     h0p);
            fma2(aB, wp[2 * i + 1], h1p);
            fma2(aC, wp[2 * i + 2], h2p);
            fma2(aD, wp[2 * i + 3], h3p);
        }
        float2 fA = unpack2(aA), fB = unpack2(aB);
        float2 fC = unpack2(aC), fD = unpack2(aD);
        float acc = ((fA.x + fA.y) + (fB.x + fB.y)) +
                    ((fC.x + fC.y) + (fD.x + fD.y));
        acc += __shfl_down_sync(0xffffffffu, acc, 4, 8);
        acc += __shfl_down_sync(0xffffffffu, acc, 2, 8);
        acc += __shfl_down_sync(0xffffffffu, acc, 1, 8);
        if (lane8 == 0) gbuf[task] = acc + xwv;
        __syncthreads();

        // activations in warp 0: lane = gate*8 + jj (parallel across lanes)
        if (tid < 32) {
            float gval = gbuf[tid];
            float act;
            if ((tid >> 3) == 2) act = fast_tanh(gval);   // g gate
            else                 act = fast_sig(gval);    // i,f,o
            float xf = __shfl_sync(0xffffffffu, act, tid + 8);
            float xg = __shfl_sync(0xffffffffu, act, tid + 16);
            float xo = __shfl_sync(0xffffffffu, act, tid + 24);
            float hv = 0.f;
            if (tid < JPB) {
                c_reg = fmaf(xf, c_reg, act * xg);   // act = sigmoid(i)
                hv = xo * fast_tanh(c_reg);
                hvx[tid] = hv;
            }
            __syncwarp();
            if (tid < 2) {   // exchange store FIRST (critical path), 2x16B one warp
                float4 p = *((const float4*)&hvx[0] + tid);
                stg_relaxed_v4((float4*)&g_hx[dir][s][blk][0] + tid, p);
            }
            if (tid < JPB)
                g_lstm[t][dir * HDIM + j0 + tid] = hv;  // for tag kernel (off-path)
        }
        // The post-reduce __syncthreads orders this step's hbuf reads
        // before next step's hbuf writes.
    }
}

// ---------------- Kernel C: tag projection ----------------
__global__ __launch_bounds__(256) void tag_kernel(
    const float* __restrict__ w_tag, const float* __restrict__ b_tag)
{
    int t = blockIdx.x;
    __shared__ __align__(16) float row[2 * HDIM];
    int tid = threadIdx.x; // 256
    ((float4*)row)[tid] = ((const float4*)&g_lstm[t][0])[tid];
    __syncthreads();

    int lane8 = tid & 7;
    int k = tid >> 3;     // 0..31
    const float4* wr = (const float4*)(w_tag + (size_t)k * 2 * HDIM);
    const float4* r4 = (const float4*)row;
    float acc = 0.f;
#pragma unroll
    for (int i = 0; i < 32; i++) {
        float4 w = wr[lane8 + 8 * i];
        float4 x = r4[lane8 + 8 * i];
        acc = fmaf(w.x, x.x, acc);
        acc = fmaf(w.y, x.y, acc);
        acc = fmaf(w.z, x.z, acc);
        acc = fmaf(w.w, x.w, acc);
    }
    acc += __shfl_down_sync(0xffffffffu, acc, 4, 8);
    acc += __shfl_down_sync(0xffffffffu, acc, 2, 8);
    acc += __shfl_down_sync(0xffffffffu, acc, 1, 8);
    if (lane8 == 0) g_feats[t][k] = acc + b_tag[k];
}

// ---------------- Kernel D: Viterbi decode (warp-per-next-tag) ----------
// R9-verified (rel_err 0.0): 32 warps; warp n owns next-tag n, lane p =
// prev-tag. Argmax via one REDUX.MAX on a monotone key, low 5 bits carry
// (31-p) for first-max tie-break. Double-buffered fv, one barrier/step.
__global__ __launch_bounds__(1024) void viterbi_kernel(
    const float* __restrict__ trans, float* __restrict__ out)
{
    __shared__ float fv[2][KTAG];
    __shared__ unsigned char bp[TT][KTAG];
    int tid = threadIdx.x;
    int n = tid >> 5;     // next tag (warp)
    int p = tid & 31;     // prev tag (lane)

    float trv = trans[n * KTAG + p];

    if (tid < KTAG) fv[0][tid] = (tid == START_TAG) ? 0.f : NEGV;
    __syncthreads();

    for (int t = 0; t < TT; t++) {
        float feat = g_feats[t][n];                 // off-chain prefetch
        float sc = fv[t & 1][p] + trv;
        unsigned key = (fkey(sc) & ~31u) | (31u - p);
        unsigned m = __reduce_max_sync(0xffffffffu, key);
        int bestp = 31 - (int)(m & 31u);
        float best = __shfl_sync(0xffffffffu, sc, bestp);
        if (p == 0) {
            bp[t][n] = (unsigned char)bestp;
            fv[(t + 1) & 1][n] = best + feat;
        }
        __syncthreads();
    }

    if (n == 0) {
        float tv = fv[TT & 1][p] + trans[STOP_TAG * KTAG + p];
        unsigned key = (fkey(tv) & ~31u) | (31u - p);
        unsigned m = __reduce_max_sync(0xffffffffu, key);
        int bidx = 31 - (int)(m & 31u);
        float bv = __shfl_sync(0xffffffffu, tv, bidx);
        if (p == 0) {
            out[0] = bv;                     // score
            out[TT] = (float)bidx;           // path[T-1] = best
            int tag = bidx;
            for (int t = TT - 1; t >= 1; t--) {
                tag = bp[t][tag];
                out[t] = (float)tag;         // path[t-1]
            }
        }
    }
}

// ---------------- launch ----------------
extern "C" void kernel_launch(void* const* d_in, const int* in_sizes, int n_in,
                              void* d_out, int out_size)
{
    const int*   sentence = (const int*)d_in[0];
    const float* embed    = (const float*)d_in[1];
    const float* w_ih_f   = (const float*)d_in[2];
    const float* w_hh_f   = (const float*)d_in[3];
    const float* b_ih_f   = (const float*)d_in[4];
    const float* b_hh_f   = (const float*)d_in[5];
    const float* w_ih_b   = (const float*)d_in[6];
    const float* w_hh_b   = (const float*)d_in[7];
    const float* b_ih_b   = (const float*)d_in[8];
    const float* b_hh_b   = (const float*)d_in[9];
    const float* h0       = (const float*)d_in[10];
    const float* c0       = (const float*)d_in[11];
    const float* w_tag    = (const float*)d_in[12];
    const float* b_tag    = (const float*)d_in[13];
    const float* trans    = (const float*)d_in[14];
    float* out = (float*)d_out;

    // poison exchange slots: 131072 float4 / 256 = 512 blocks
    poison_kernel<<<512, 256>>>();

    dim3 ggrid(G4 / 128, TT / 128, 2);   // 16 x 4 x 2 = 128 blocks
    gemm_xw_kernel<<<ggrid, 256>>>(sentence, embed,
                                   w_ih_f, b_ih_f, b_hh_f,
                                   w_ih_b, b_ih_b, b_hh_b);

    lstm_kernel<<<2 * NBD, LSTM_THREADS>>>(w_hh_f, w_hh_b, h0, c0);

    tag_kernel<<<TT, 256>>>(w_tag, b_tag);

    viterbi_kernel<<<1, 1024>>>(trans, out);
}

// round 11
// speedup vs baseline: 1.4026x; 1.4026x over previous
#include <cuda_runtime.h>
#include <cstdint>

// Problem constants
#define TT   512      // sequence length
#define EE   1024     // embedding dim
#define HDIM 512      // per-direction hidden
#define G4   2048     // 4*HDIM gate rows
#define KTAG 32       // tags
#define NEGV (-10000.0f)
#define START_TAG 30
#define STOP_TAG  31

// LSTM recurrent kernel config
#define NBD  64              // blocks per direction
#define JPB  (HDIM / NBD)    // h-indices per block = 8
#define LSTM_THREADS 256
#define SENT 0x7FC00001u     // NaN sentinel: h = sigmoid*tanh can never be NaN

// ---------------- scratch (device globals; no allocation) ----------------
__device__ float g_xw[2][TT][G4];          // input projections + biases (scan-step indexed)
__device__ float g_lstm[TT][2 * HDIM];     // concatenated [hf | hb] (time indexed)
__device__ float g_feats[TT][KTAG];        // tag scores
__device__ float g_hx[2][TT][NBD][JPB];    // per-step h exchange slots (POISONED by GEMM prologue)

// ---------------- asm helpers ----------------
__device__ __forceinline__ float4 ldg_relaxed_v4(const float4* p) {
    float4 v;
    asm volatile("ld.global.relaxed.gpu.v4.f32 {%0,%1,%2,%3}, [%4];"
                 : "=f"(v.x), "=f"(v.y), "=f"(v.z), "=f"(v.w) : "l"(p) : "memory");
    return v;
}
__device__ __forceinline__ void stg_relaxed_v4(float4* p, float4 v) {
    asm volatile("st.global.relaxed.gpu.v4.f32 [%0], {%1,%2,%3,%4};"
                 :: "l"(p), "f"(v.x), "f"(v.y), "f"(v.z), "f"(v.w) : "memory");
}
__device__ __forceinline__ bool has_sent(float4 v) {
    return (__float_as_uint(v.x) == SENT) | (__float_as_uint(v.y) == SENT) |
           (__float_as_uint(v.z) == SENT) | (__float_as_uint(v.w) == SENT);
}
// packed f32x2 FMA (sm_100+; ptxas never emits this from C++)
__device__ __forceinline__ void fma2(uint64_t& d, uint64_t a, uint64_t b) {
    asm("fma.rn.f32x2 %0, %1, %2, %0;" : "+l"(d) : "l"(a), "l"(b));
}
__device__ __forceinline__ uint64_t pack2(float x, float y) {
    uint64_t r; asm("mov.b64 %0, {%1,%2};" : "=l"(r) : "f"(x), "f"(y)); return r;
}
__device__ __forceinline__ float2 unpack2(uint64_t v) {
    float2 f; asm("mov.b64 {%0,%1}, %2;" : "=f"(f.x), "=f"(f.y) : "l"(v)); return f;
}
__device__ __forceinline__ void lds_v2_u64(uint32_t addr, uint64_t& x, uint64_t& y) {
    asm volatile("ld.shared.v2.b64 {%0,%1}, [%2];" : "=l"(x), "=l"(y) : "r"(addr));
}
// fast activations: MUFU-based, rel err ~1e-6 (safe vs argmax margins)
__device__ __forceinline__ float fast_sig(float x) {
    return __fdividef(1.f, 1.f + __expf(-x));
}
__device__ __forceinline__ float fast_tanh(float x) {
    return 1.f - __fdividef(2.f, __expf(2.f * x) + 1.f);
}
// monotone float -> unsigned key (order-preserving)
__device__ __forceinline__ unsigned fkey(float x) {
    unsigned b = __float_as_uint(x);
    return (b & 0x80000000u) ? ~b : (b | 0x80000000u);
}

// ---------------- Kernel A: poison prologue + embed-gather + GEMM --------
// 128x128 tile, 8x8 per thread, packed f32x2 FMA inner loop. Each block
// first poisons its 1/128 slice of g_hx (LSTM launches after this kernel
// completes, so ordering is stream-guaranteed).
__global__ __launch_bounds__(256, 1) void gemm_xw_kernel(
    const int* __restrict__ sentence,
    const float* __restrict__ embed,
    const float* __restrict__ w_ih_f, const float* __restrict__ b_ih_f,
    const float* __restrict__ b_hh_f,
    const float* __restrict__ w_ih_b, const float* __restrict__ b_ih_b,
    const float* __restrict__ b_hh_b)
{
    // ---- poison g_hx slice: 131072 float4 / 128 blocks = 1024 each ----
    {
        int bflat = (blockIdx.z * gridDim.y + blockIdx.y) * gridDim.x + blockIdx.x;
        float4* p = (float4*)g_hx + (size_t)bflat * 1024;
        float4 v = make_float4(__uint_as_float(SENT), __uint_as_float(SENT),
                               __uint_as_float(SENT), __uint_as_float(SENT));
#pragma unroll
        for (int i = 0; i < 4; i++) p[i * 256 + threadIdx.x] = v;
    }

    int dir = blockIdx.z;
    const float* W  = dir ? w_ih_b : w_ih_f;
    const float* Bi = dir ? b_ih_b : b_ih_f;
    const float* Bh = dir ? b_hh_b : b_hh_f;

    int n0 = blockIdx.x * 128;   // gate-row tile
    int m0 = blockIdx.y * 128;   // scan-step tile

    __shared__ __align__(16) float As[8][128];
    __shared__ __align__(16) float Bs[8][128];

    int tid = threadIdx.x;
    int tx = tid & 15;           // 8 output cols
    int ty = tid >> 4;           // 8 output rows
    int lrow = tid >> 1;         // load row
    int lq   = tid & 1;          // float4 within 8-wide k slab

    int sglob = m0 + lrow;                       // scan step
    int sidx  = dir ? (TT - 1 - sglob) : sglob;  // token consumed there
    const float* aptr = embed + (size_t)sentence[sidx] * EE + lq * 4;
    const float* bptr = W + (size_t)(n0 + lrow) * EE + lq * 4;

    uint64_t acc2[8][4];
#pragma unroll
    for (int i = 0; i < 8; i++)
#pragma unroll
        for (int j = 0; j < 4; j++) acc2[i][j] = 0ull;

    uint32_t bs_base = (uint32_t)__cvta_generic_to_shared(&Bs[0][tx * 8]);
    uint32_t as_base = (uint32_t)__cvta_generic_to_shared(&As[0][ty * 8]);

    float4 a_nx = *(const float4*)aptr;
    float4 b_nx = *(const float4*)bptr;

    for (int k0 = 0; k0 < EE; k0 += 8) {
        As[lq * 4 + 0][lrow] = a_nx.x; As[lq * 4 + 1][lrow] = a_nx.y;
        As[lq * 4 + 2][lrow] = a_nx.z; As[lq * 4 + 3][lrow] = a_nx.w;
        Bs[lq * 4 + 0][lrow] = b_nx.x; Bs[lq * 4 + 1][lrow] = b_nx.y;
        Bs[lq * 4 + 2][lrow] = b_nx.z; Bs[lq * 4 + 3][lrow] = b_nx.w;
        __syncthreads();

        if (k0 + 8 < EE) {
            a_nx = *(const float4*)(aptr + k0 + 8);
            b_nx = *(const float4*)(bptr + k0 + 8);
        }

#pragma unroll
        for (int k = 0; k < 8; k++) {
            uint64_t a01, a23, a45, a67;
            lds_v2_u64(as_base + k * 512,      a01, a23);
            lds_v2_u64(as_base + k * 512 + 16, a45, a67);
            uint64_t b01, b23, b45, b67;
            lds_v2_u64(bs_base + k * 512,      b01, b23);
            lds_v2_u64(bs_base + k * 512 + 16, b45, b67);
            float2 a0 = unpack2(a01), a1 = unpack2(a23);
            float2 a2 = unpack2(a45), a3 = unpack2(a67);
            float a[8] = {a0.x, a0.y, a1.x, a1.y, a2.x, a2.y, a3.x, a3.y};
#pragma unroll
            for (int i = 0; i < 8; i++) {
                uint64_t aa = pack2(a[i], a[i]);
                fma2(acc2[i][0], aa, b01);
                fma2(acc2[i][1], aa, b23);
                fma2(acc2[i][2], aa, b45);
                fma2(acc2[i][3], aa, b67);
            }
        }
        __syncthreads();
    }

    int rbase = n0 + tx * 8;
    float4 bi0 = *(const float4*)(Bi + rbase);
    float4 bi1 = *(const float4*)(Bi + rbase + 4);
    float4 bh0 = *(const float4*)(Bh + rbase);
    float4 bh1 = *(const float4*)(Bh + rbase + 4);
    float bias[8] = {bi0.x + bh0.x, bi0.y + bh0.y, bi0.z + bh0.z, bi0.w + bh0.w,
                     bi1.x + bh1.x, bi1.y + bh1.y, bi1.z + bh1.z, bi1.w + bh1.w};
#pragma unroll
    for (int i = 0; i < 8; i++) {
        int m = m0 + ty * 8 + i;
        float2 p0 = unpack2(acc2[i][0]);
        float2 p1 = unpack2(acc2[i][1]);
        float2 p2 = unpack2(acc2[i][2]);
        float2 p3 = unpack2(acc2[i][3]);
        float4 o0 = make_float4(p0.x + bias[0], p0.y + bias[1],
                                p1.x + bias[2], p1.y + bias[3]);
        float4 o1 = make_float4(p2.x + bias[4], p2.y + bias[5],
                                p3.x + bias[6], p3.y + bias[7]);
        *(float4*)&g_xw[dir][m][rbase]     = o0;
        *(float4*)&g_xw[dir][m][rbase + 4] = o1;
    }
}

// ---------------- Kernel B: persistent recurrent LSTM --------------------
// R6-verified core. One change: polling moved to warps 4-7 (tid>=128),
// which have no end-of-step duties — all 128 poll loads issue at bar2+0
// instead of warp 0's polls trailing its activation/store tail.
// Writer still emits the whole 32B payload as TWO 16B relaxed stores from
// ONE warp. Self-throttled DEPENDENT poll (pipelined poll saturates L2).
__global__ __launch_bounds__(LSTM_THREADS, 1) void lstm_kernel(
    const float* __restrict__ w_hh_f,
    const float* __restrict__ w_hh_b,
    const float* __restrict__ h0,
    const float* __restrict__ c0)
{
    __shared__ __align__(16) float hbuf[HDIM];
    __shared__ float gbuf[32];
    __shared__ __align__(16) float hvx[8];

    int bid = blockIdx.x;
    int dir = bid / NBD;
    int blk = bid % NBD;
    int j0  = blk * JPB;
    int tid = threadIdx.x;
    int lane8 = tid & 7;
    int task  = tid >> 3;        // 0..31 = gi*8 + jj
    int gi    = task >> 3;
    int jj    = task & 7;

    const float* w_hh = dir ? w_hh_b : w_hh_f;

    // Weights into registers as packed f32x2 pairs
    const float4* wrow = (const float4*)(w_hh + (size_t)(gi * HDIM + j0 + jj) * HDIM);
    uint64_t wp[32];
#pragma unroll
    for (int i = 0; i < 16; i++) {
        float4 w4 = wrow[lane8 + 8 * i];
        wp[2 * i]     = pack2(w4.x, w4.y);
        wp[2 * i + 1] = pack2(w4.z, w4.w);
    }

    float c_reg = (tid < JPB) ? c0[dir * HDIM + j0 + tid] : 0.f;

    int pt = tid - 128;          // poller index (valid for tid>=128)
    int pw = pt >> 1;            // writer block this poller tracks
    int pq = pt & 1;             // which 16B chunk of that writer's payload
    const float* xwbase = &g_xw[dir][0][gi * HDIM + j0 + jj];
    uint32_t h_base = (uint32_t)__cvta_generic_to_shared(&hbuf[0]) + lane8 * 16;

    for (int s = 0; s < TT; s++) {
        int t = dir ? (TT - 1 - s) : s;

        // prefetch xw before the spin so its latency hides under the poll
        float xwv = 0.f;
        if (lane8 == 0) xwv = __ldcg(xwbase + (size_t)s * G4);

        if (s == 0) {
            if (tid >= 128)
                ((float4*)hbuf)[pt] = ((const float4*)(h0 + dir * HDIM))[pt];
        } else if (tid >= 128) {
            // warps 4-7: no end-of-step duties, polls start at bar2+0
            const float4* src = (const float4*)&g_hx[dir][s - 1][pw][0] + pq;
            float4 hv4;
            do { hv4 = ldg_relaxed_v4(src); } while (has_sent(hv4));
            *((float4*)&hbuf[pw * 8] + pq) = hv4;
        }
        __syncthreads();   // bar1: hbuf ready (prior-step reads ordered by bar2)

        // h . w_row with packed f32x2 FMA, 4 independent chains
        uint64_t aA = 0ull, aB = 0ull, aC = 0ull, aD = 0ull;
#pragma unroll
        for (int i = 0; i < 16; i += 2) {
            uint64_t h0p, h1p, h2p, h3p;
            lds_v2_u64(h_base + i * 128, h0p, h1p);
            lds_v2_u64(h_base + i * 128 + 128, h2p, h3p);
            fma2(aA, wp[2 * i],     h0p);
            fma2(aB, wp[2 * i + 1], h1p);
            fma2(aC, wp[2 * i + 2], h2p);
            fma2(aD, wp[2 * i + 3], h3p);
        }
        float2 fA = unpack2(aA), fB = unpack2(aB);
        float2 fC = unpack2(aC), fD = unpack2(aD);
        float acc = ((fA.x + fA.y) + (fB.x + fB.y)) +
                    ((fC.x + fC.y) + (fD.x + fD.y));
        acc += __shfl_down_sync(0xffffffffu, acc, 4, 8);
        acc += __shfl_down_sync(0xffffffffu, acc, 2, 8);
        acc += __shfl_down_sync(0xffffffffu, acc, 1, 8);
        if (lane8 == 0) gbuf[task] = acc + xwv;
        __syncthreads();   // bar2: gbuf ready; also orders hbuf reads vs next writes

        // activations in warp 0: lane = gate*8 + jj (parallel across lanes)
        if (tid < 32) {
            float gval = gbuf[tid];
            float act;
            if ((tid >> 3) == 2) act = fast_tanh(gval);   // g gate
            else                 act = fast_sig(gval);    // i,f,o
            float xf = __shfl_sync(0xffffffffu, act, tid + 8);
            float xg = __shfl_sync(0xffffffffu, act, tid + 16);
            float xo = __shfl_sync(0xffffffffu, act, tid + 24);
            float hv = 0.f;
            if (tid < JPB) {
                c_reg = fmaf(xf, c_reg, act * xg);   // act = sigmoid(i)
                hv = xo * fast_tanh(c_reg);
                hvx[tid] = hv;
            }
            __syncwarp();
            if (tid < 2) {   // exchange store FIRST (critical path), 2x16B one warp
                float4 p = *((const float4*)&hvx[0] + tid);
                stg_relaxed_v4((float4*)&g_hx[dir][s][blk][0] + tid, p);
            }
            if (tid < JPB)
                g_lstm[t][dir * HDIM + j0 + tid] = hv;  // for tag kernel (off-path)
        }
    }
}

// ---------------- Kernel C: tag projection (clock canary: ~9us) ----------
__global__ __launch_bounds__(256) void tag_kernel(
    const float* __restrict__ w_tag, const float* __restrict__ b_tag)
{
    int t = blockIdx.x;
    __shared__ __align__(16) float row[2 * HDIM];
    int tid = threadIdx.x; // 256
    ((float4*)row)[tid] = ((const float4*)&g_lstm[t][0])[tid];
    __syncthreads();

    int lane8 = tid & 7;
    int k = tid >> 3;     // 0..31
    const float4* wr = (const float4*)(w_tag + (size_t)k * 2 * HDIM);
    const float4* r4 = (const float4*)row;
    float acc = 0.f;
#pragma unroll
    for (int i = 0; i < 32; i++) {
        float4 w = wr[lane8 + 8 * i];
        float4 x = r4[lane8 + 8 * i];
        acc = fmaf(w.x, x.x, acc);
        acc = fmaf(w.y, x.y, acc);
        acc = fmaf(w.z, x.z, acc);
        acc = fmaf(w.w, x.w, acc);
    }
    acc += __shfl_down_sync(0xffffffffu, acc, 4, 8);
    acc += __shfl_down_sync(0xffffffffu, acc, 2, 8);
    acc += __shfl_down_sync(0xffffffffu, acc, 1, 8);
    if (lane8 == 0) g_feats[t][k] = acc + b_tag[k];
}

// ---------------- Kernel D: Viterbi decode (warp-per-next-tag) ----------
// R9-verified: warp n owns next-tag n, lane p = prev-tag. Argmax via one
// REDUX.MAX on a monotone key, low 5 bits carry (31-p) for first-max
// tie-break. Double-buffered fv, one barrier per step.
__global__ __launch_bounds__(1024) void viterbi_kernel(
    const float* __restrict__ trans, float* __restrict__ out)
{
    __shared__ float fv[2][KTAG];
    __shared__ unsigned char bp[TT][KTAG];
    int tid = threadIdx.x;
    int n = tid >> 5;     // next tag (warp)
    int p = tid & 31;     // prev tag (lane)

    float trv = trans[n * KTAG + p];

    if (tid < KTAG) fv[0][tid] = (tid == START_TAG) ? 0.f : NEGV;
    __syncthreads();

    for (int t = 0; t < TT; t++) {
        float feat = g_feats[t][n];                 // off-chain prefetch
        float sc = fv[t & 1][p] + trv;
        unsigned key = (fkey(sc) & ~31u) | (31u - p);
        unsigned m = __reduce_max_sync(0xffffffffu, key);
        int bestp = 31 - (int)(m & 31u);
        float best = __shfl_sync(0xffffffffu, sc, bestp);
        if (p == 0) {
            bp[t][n] = (unsigned char)bestp;
            fv[(t + 1) & 1][n] = best + feat;
        }
        __syncthreads();
    }

    if (n == 0) {
        float tv = fv[TT & 1][p] + trans[STOP_TAG * KTAG + p];
        unsigned key = (fkey(tv) & ~31u) | (31u - p);
        unsigned m = __reduce_max_sync(0xffffffffu, key);
        int bidx = 31 - (int)(m & 31u);
        float bv = __shfl_sync(0xffffffffu, tv, bidx);
        if (p == 0) {
            out[0] = bv;                     // score
            out[TT] = (float)bidx;           // path[T-1] = best
            int tag = bidx;
            for (int t = TT - 1; t >= 1; t--) {
                tag = bp[t][tag];
                out[t] = (float)tag;         // path[t-1]
            }
        }
    }
}

// ---------------- launch ----------------
extern "C" void kernel_launch(void* const* d_in, const int* in_sizes, int n_in,
                              void* d_out, int out_size)
{
    const int*   sentence = (const int*)d_in[0];
    const float* embed    = (const float*)d_in[1];
    const float* w_ih_f   = (const float*)d_in[2];
    const float* w_hh_f   = (const float*)d_in[3];
    const float* b_ih_f   = (const float*)d_in[4];
    const float* b_hh_f   = (const float*)d_in[5];
    const float* w_ih_b   = (const float*)d_in[6];
    const float* w_hh_b   = (const float*)d_in[7];
    const float* b_ih_b   = (const float*)d_in[8];
    const float* b_hh_b   = (const float*)d_in[9];
    const float* h0       = (const float*)d_in[10];
    const float* c0       = (const float*)d_in[11];
    const float* w_tag    = (const float*)d_in[12];
    const float* b_tag    = (const float*)d_in[13];
    const float* trans    = (const float*)d_in[14];
    float* out = (float*)d_out;

    // GEMM prologue poisons g_hx; LSTM launches after, ordering guaranteed.
    dim3 ggrid(G4 / 128, TT / 128, 2);   // 16 x 4 x 2 = 128 blocks
    gemm_xw_kernel<<<ggrid, 256>>>(sentence, embed,
                                   w_ih_f, b_ih_f, b_hh_f,
                                   w_ih_b, b_ih_b, b_hh_b);

    lstm_kernel<<<2 * NBD, LSTM_THREADS>>>(w_hh_f, w_hh_b, h0, c0);

    tag_kernel<<<TT, 256>>>(w_tag, b_tag);

    viterbi_kernel<<<1, 1024>>>(trans, out);
}

// round 12
// speedup vs baseline: 1.6745x; 1.1939x over previous
#include <cuda_runtime.h>
#include <cstdint>

// Problem constants
#define TT   512      // sequence length
#define EE   1024     // embedding dim
#define HDIM 512      // per-direction hidden
#define G4   2048     // 4*HDIM gate rows
#define KTAG 32       // tags
#define NEGV (-10000.0f)
#define START_TAG 30
#define STOP_TAG  31

// LSTM recurrent kernel config
#define NBD  64              // blocks per direction
#define JPB  (HDIM / NBD)    // h-indices per block = 8
#define LSTM_THREADS 256
#define SENT 0x7FC00001u     // NaN sentinel: h = sigmoid*tanh can never be NaN

// ---------------- scratch (device globals; no allocation) ----------------
__device__ float g_xw[2][TT][G4];          // input projections + biases (scan-step indexed)
__device__ float g_lstm[TT][2 * HDIM];     // concatenated [hf | hb] (time indexed)
__device__ float g_feats[TT][KTAG];        // tag scores
__device__ float g_hx[2][TT][NBD][JPB];    // per-step h exchange slots (POISONED by GEMM prologue)

// ---------------- asm helpers ----------------
__device__ __forceinline__ float4 ldg_relaxed_v4(const float4* p) {
    float4 v;
    asm volatile("ld.global.relaxed.gpu.v4.f32 {%0,%1,%2,%3}, [%4];"
                 : "=f"(v.x), "=f"(v.y), "=f"(v.z), "=f"(v.w) : "l"(p) : "memory");
    return v;
}
__device__ __forceinline__ void stg_relaxed_v4(float4* p, float4 v) {
    asm volatile("st.global.relaxed.gpu.v4.f32 [%0], {%1,%2,%3,%4};"
                 :: "l"(p), "f"(v.x), "f"(v.y), "f"(v.z), "f"(v.w) : "memory");
}
__device__ __forceinline__ bool has_sent(float4 v) {
    return (__float_as_uint(v.x) == SENT) | (__float_as_uint(v.y) == SENT) |
           (__float_as_uint(v.z) == SENT) | (__float_as_uint(v.w) == SENT);
}
// packed f32x2 FMA (sm_100+; ptxas never emits this from C++)
__device__ __forceinline__ void fma2(uint64_t& d, uint64_t a, uint64_t b) {
    asm("fma.rn.f32x2 %0, %1, %2, %0;" : "+l"(d) : "l"(a), "l"(b));
}
__device__ __forceinline__ uint64_t pack2(float x, float y) {
    uint64_t r; asm("mov.b64 %0, {%1,%2};" : "=l"(r) : "f"(x), "f"(y)); return r;
}
__device__ __forceinline__ float2 unpack2(uint64_t v) {
    float2 f; asm("mov.b64 {%0,%1}, %2;" : "=f"(f.x), "=f"(f.y) : "l"(v)); return f;
}
__device__ __forceinline__ void lds_v2_u64(uint32_t addr, uint64_t& x, uint64_t& y) {
    asm volatile("ld.shared.v2.b64 {%0,%1}, [%2];" : "=l"(x), "=l"(y) : "r"(addr));
}
// fast activations: MUFU-based, rel err ~1e-6 (safe vs argmax margins)
__device__ __forceinline__ float fast_sig(float x) {
    return __fdividef(1.f, 1.f + __expf(-x));
}
__device__ __forceinline__ float fast_tanh(float x) {
    return 1.f - __fdividef(2.f, __expf(2.f * x) + 1.f);
}
// monotone float -> unsigned key (order-preserving)
__device__ __forceinline__ unsigned fkey(float x) {
    unsigned b = __float_as_uint(x);
    return (b & 0x80000000u) ? ~b : (b | 0x80000000u);
}

// ---------------- Kernel A: poison prologue + embed-gather + GEMM --------
// 128x128 tile, 8x8 per thread, packed f32x2 FMA inner loop. Each block
// first poisons its 1/128 slice of g_hx (LSTM launches after this kernel
// completes, so ordering is stream-guaranteed).
__global__ __launch_bounds__(256, 1) void gemm_xw_kernel(
    const int* __restrict__ sentence,
    const float* __restrict__ embed,
    const float* __restrict__ w_ih_f, const float* __restrict__ b_ih_f,
    const float* __restrict__ b_hh_f,
    const float* __restrict__ w_ih_b, const float* __restrict__ b_ih_b,
    const float* __restrict__ b_hh_b)
{
    // ---- poison g_hx slice: 131072 float4 / 128 blocks = 1024 each ----
    {
        int bflat = (blockIdx.z * gridDim.y + blockIdx.y) * gridDim.x + blockIdx.x;
        float4* p = (float4*)g_hx + (size_t)bflat * 1024;
        float4 v = make_float4(__uint_as_float(SENT), __uint_as_float(SENT),
                               __uint_as_float(SENT), __uint_as_float(SENT));
#pragma unroll
        for (int i = 0; i < 4; i++) p[i * 256 + threadIdx.x] = v;
    }

    int dir = blockIdx.z;
    const float* W  = dir ? w_ih_b : w_ih_f;
    const float* Bi = dir ? b_ih_b : b_ih_f;
    const float* Bh = dir ? b_hh_b : b_hh_f;

    int n0 = blockIdx.x * 128;   // gate-row tile
    int m0 = blockIdx.y * 128;   // scan-step tile

    __shared__ __align__(16) float As[8][128];
    __shared__ __align__(16) float Bs[8][128];

    int tid = threadIdx.x;
    int tx = tid & 15;           // 8 output cols
    int ty = tid >> 4;           // 8 output rows
    int lrow = tid >> 1;         // load row
    int lq   = tid & 1;          // float4 within 8-wide k slab

    int sglob = m0 + lrow;                       // scan step
    int sidx  = dir ? (TT - 1 - sglob) : sglob;  // token consumed there
    const float* aptr = embed + (size_t)sentence[sidx] * EE + lq * 4;
    const float* bptr = W + (size_t)(n0 + lrow) * EE + lq * 4;

    uint64_t acc2[8][4];
#pragma unroll
    for (int i = 0; i < 8; i++)
#pragma unroll
        for (int j = 0; j < 4; j++) acc2[i][j] = 0ull;

    uint32_t bs_base = (uint32_t)__cvta_generic_to_shared(&Bs[0][tx * 8]);
    uint32_t as_base = (uint32_t)__cvta_generic_to_shared(&As[0][ty * 8]);

    float4 a_nx = *(const float4*)aptr;
    float4 b_nx = *(const float4*)bptr;

    for (int k0 = 0; k0 < EE; k0 += 8) {
        As[lq * 4 + 0][lrow] = a_nx.x; As[lq * 4 + 1][lrow] = a_nx.y;
        As[lq * 4 + 2][lrow] = a_nx.z; As[lq * 4 + 3][lrow] = a_nx.w;
        Bs[lq * 4 + 0][lrow] = b_nx.x; Bs[lq * 4 + 1][lrow] = b_nx.y;
        Bs[lq * 4 + 2][lrow] = b_nx.z; Bs[lq * 4 + 3][lrow] = b_nx.w;
        __syncthreads();

        if (k0 + 8 < EE) {
            a_nx = *(const float4*)(aptr + k0 + 8);
            b_nx = *(const float4*)(bptr + k0 + 8);
        }

#pragma unroll
        for (int k = 0; k < 8; k++) {
            uint64_t a01, a23, a45, a67;
            lds_v2_u64(as_base + k * 512,      a01, a23);
            lds_v2_u64(as_base + k * 512 + 16, a45, a67);
            uint64_t b01, b23, b45, b67;
            lds_v2_u64(bs_base + k * 512,      b01, b23);
            lds_v2_u64(bs_base + k * 512 + 16, b45, b67);
            float2 a0 = unpack2(a01), a1 = unpack2(a23);
            float2 a2 = unpack2(a45), a3 = unpack2(a67);
            float a[8] = {a0.x, a0.y, a1.x, a1.y, a2.x, a2.y, a3.x, a3.y};
#pragma unroll
            for (int i = 0; i < 8; i++) {
                uint64_t aa = pack2(a[i], a[i]);
                fma2(acc2[i][0], aa, b01);
                fma2(acc2[i][1], aa, b23);
                fma2(acc2[i][2], aa, b45);
                fma2(acc2[i][3], aa, b67);
            }
        }
        __syncthreads();
    }

    int rbase = n0 + tx * 8;
    float4 bi0 = *(const float4*)(Bi + rbase);
    float4 bi1 = *(const float4*)(Bi + rbase + 4);
    float4 bh0 = *(const float4*)(Bh + rbase);
    float4 bh1 = *(const float4*)(Bh + rbase + 4);
    float bias[8] = {bi0.x + bh0.x, bi0.y + bh0.y, bi0.z + bh0.z, bi0.w + bh0.w,
                     bi1.x + bh1.x, bi1.y + bh1.y, bi1.z + bh1.z, bi1.w + bh1.w};
#pragma unroll
    for (int i = 0; i < 8; i++) {
        int m = m0 + ty * 8 + i;
        float2 p0 = unpack2(acc2[i][0]);
        float2 p1 = unpack2(acc2[i][1]);
        float2 p2 = unpack2(acc2[i][2]);
        float2 p3 = unpack2(acc2[i][3]);
        float4 o0 = make_float4(p0.x + bias[0], p0.y + bias[1],
                                p1.x + bias[2], p1.y + bias[3]);
        float4 o1 = make_float4(p2.x + bias[4], p2.y + bias[5],
                                p3.x + bias[6], p3.y + bias[7]);
        *(float4*)&g_xw[dir][m][rbase]     = o0;
        *(float4*)&g_xw[dir][m][rbase + 4] = o1;
    }
}

// ---------------- Kernel B: persistent recurrent LSTM --------------------
// R6-verified core; polling on warps 4-7 (no end-of-step duties). Writer
// emits the whole 32B payload as TWO 16B relaxed stores from ONE warp.
// Self-throttled DEPENDENT poll (pipelined poll saturates L2 — never again).
__global__ __launch_bounds__(LSTM_THREADS, 1) void lstm_kernel(
    const float* __restrict__ w_hh_f,
    const float* __restrict__ w_hh_b,
    const float* __restrict__ h0,
    const float* __restrict__ c0)
{
    __shared__ __align__(16) float hbuf[HDIM];
    __shared__ float gbuf[32];
    __shared__ __align__(16) float hvx[8];

    int bid = blockIdx.x;
    int dir = bid / NBD;
    int blk = bid % NBD;
    int j0  = blk * JPB;
    int tid = threadIdx.x;
    int lane8 = tid & 7;
    int task  = tid >> 3;        // 0..31 = gi*8 + jj
    int gi    = task >> 3;
    int jj    = task & 7;

    const float* w_hh = dir ? w_hh_b : w_hh_f;

    // Weights into registers as packed f32x2 pairs
    const float4* wrow = (const float4*)(w_hh + (size_t)(gi * HDIM + j0 + jj) * HDIM);
    uint64_t wp[32];
#pragma unroll
    for (int i = 0; i < 16; i++) {
        float4 w4 = wrow[lane8 + 8 * i];
        wp[2 * i]     = pack2(w4.x, w4.y);
        wp[2 * i + 1] = pack2(w4.z, w4.w);
    }

    float c_reg = (tid < JPB) ? c0[dir * HDIM + j0 + tid] : 0.f;

    int pt = tid - 128;          // poller index (valid for tid>=128)
    int pw = pt >> 1;            // writer block this poller tracks
    int pq = pt & 1;             // which 16B chunk of that writer's payload
    const float* xwbase = &g_xw[dir][0][gi * HDIM + j0 + jj];
    uint32_t h_base = (uint32_t)__cvta_generic_to_shared(&hbuf[0]) + lane8 * 16;

    for (int s = 0; s < TT; s++) {
        int t = dir ? (TT - 1 - s) : s;

        // prefetch xw before the spin so its latency hides under the poll
        float xwv = 0.f;
        if (lane8 == 0) xwv = __ldcg(xwbase + (size_t)s * G4);

        if (s == 0) {
            if (tid >= 128)
                ((float4*)hbuf)[pt] = ((const float4*)(h0 + dir * HDIM))[pt];
        } else if (tid >= 128) {
            // warps 4-7: no end-of-step duties, polls start at bar2+0
            const float4* src = (const float4*)&g_hx[dir][s - 1][pw][0] + pq;
            float4 hv4;
            do { hv4 = ldg_relaxed_v4(src); } while (has_sent(hv4));
            *((float4*)&hbuf[pw * 8] + pq) = hv4;
        }
        __syncthreads();   // bar1: hbuf ready (prior-step reads ordered by bar2)

        // h . w_row with packed f32x2 FMA, 4 independent chains
        uint64_t aA = 0ull, aB = 0ull, aC = 0ull, aD = 0ull;
#pragma unroll
        for (int i = 0; i < 16; i += 2) {
            uint64_t h0p, h1p, h2p, h3p;
            lds_v2_u64(h_base + i * 128, h0p, h1p);
            lds_v2_u64(h_base + i * 128 + 128, h2p, h3p);
            fma2(aA, wp[2 * i],     h0p);
            fma2(aB, wp[2 * i + 1], h1p);
            fma2(aC, wp[2 * i + 2], h2p);
            fma2(aD, wp[2 * i + 3], h3p);
        }
        float2 fA = unpack2(aA), fB = unpack2(aB);
        float2 fC = unpack2(aC), fD = unpack2(aD);
        float acc = ((fA.x + fA.y) + (fB.x + fB.y)) +
                    ((fC.x + fC.y) + (fD.x + fD.y));
        acc += __shfl_down_sync(0xffffffffu, acc, 4, 8);
        acc += __shfl_down_sync(0xffffffffu, acc, 2, 8);
        acc += __shfl_down_sync(0xffffffffu, acc, 1, 8);
        if (lane8 == 0) gbuf[task] = acc + xwv;
        __syncthreads();   // bar2: gbuf ready; also orders hbuf reads vs next writes

        // activations in warp 0: lane = gate*8 + jj (parallel across lanes)
        if (tid < 32) {
            float gval = gbuf[tid];
            float act;
            if ((tid >> 3) == 2) act = fast_tanh(gval);   // g gate
            else                 act = fast_sig(gval);    // i,f,o
            float xf = __shfl_sync(0xffffffffu, act, tid + 8);
            float xg = __shfl_sync(0xffffffffu, act, tid + 16);
            float xo = __shfl_sync(0xffffffffu, act, tid + 24);
            float hv = 0.f;
            if (tid < JPB) {
                c_reg = fmaf(xf, c_reg, act * xg);   // act = sigmoid(i)
                hv = xo * fast_tanh(c_reg);
                hvx[tid] = hv;
            }
            __syncwarp();
            if (tid < 2) {   // exchange store FIRST (critical path), 2x16B one warp
                float4 p = *((const float4*)&hvx[0] + tid);
                stg_relaxed_v4((float4*)&g_hx[dir][s][blk][0] + tid, p);
            }
            if (tid < JPB)
                g_lstm[t][dir * HDIM + j0 + tid] = hv;  // for tag kernel (off-path)
        }
    }
}

// ---------------- Kernel C: tag projection (clock canary: ~9us) ----------
__global__ __launch_bounds__(256) void tag_kernel(
    const float* __restrict__ w_tag, const float* __restrict__ b_tag)
{
    int t = blockIdx.x;
    __shared__ __align__(16) float row[2 * HDIM];
    int tid = threadIdx.x; // 256
    ((float4*)row)[tid] = ((const float4*)&g_lstm[t][0])[tid];
    __syncthreads();

    int lane8 = tid & 7;
    int k = tid >> 3;     // 0..31
    const float4* wr = (const float4*)(w_tag + (size_t)k * 2 * HDIM);
    const float4* r4 = (const float4*)row;
    float acc = 0.f;
#pragma unroll
    for (int i = 0; i < 32; i++) {
        float4 w = wr[lane8 + 8 * i];
        float4 x = r4[lane8 + 8 * i];
        acc = fmaf(w.x, x.x, acc);
        acc = fmaf(w.y, x.y, acc);
        acc = fmaf(w.z, x.z, acc);
        acc = fmaf(w.w, x.w, acc);
    }
    acc += __shfl_down_sync(0xffffffffu, acc, 4, 8);
    acc += __shfl_down_sync(0xffffffffu, acc, 2, 8);
    acc += __shfl_down_sync(0xffffffffu, acc, 1, 8);
    if (lane8 == 0) g_feats[t][k] = acc + b_tag[k];
}

// ---------------- Kernel D: Viterbi decode (smem-staged feats) ----------
// R11 finding: per-step g_feats GLOBAL load (L2 round trip) dominated the
// 239us runtime, not the reduction. Stage all 64KB of feats into dynamic
// shared memory up front; per-step feat read becomes an LDS.
// Warp n owns next-tag n, lane p = prev-tag; argmax via one REDUX.MAX on a
// monotone key (low 5 bits carry 31-p for first-max tie-break).
extern __shared__ float vit_smem[];   // TT*KTAG floats (64 KB)
__global__ __launch_bounds__(1024) void viterbi_kernel(
    const float* __restrict__ trans, float* __restrict__ out)
{
    float* feats = vit_smem;          // [TT][KTAG]
    __shared__ float fv[2][KTAG];
    __shared__ unsigned char bp[TT][KTAG];
    int tid = threadIdx.x;
    int n = tid >> 5;     // next tag (warp)
    int p = tid & 31;     // prev tag (lane)

    // stage all feats: 16384 floats = 4096 float4, 4 per thread
    {
        float4* dst = (float4*)feats;
        const float4* src = (const float4*)g_feats;
#pragma unroll
        for (int i = 0; i < 4; i++) dst[i * 1024 + tid] = src[i * 1024 + tid];
    }

    float trv = trans[n * KTAG + p];

    if (tid < KTAG) fv[0][tid] = (tid == START_TAG) ? 0.f : NEGV;
    __syncthreads();

    for (int t = 0; t < TT; t++) {
        float sc = fv[t & 1][p] + trv;
        unsigned key = (fkey(sc) & ~31u) | (31u - p);
        unsigned m = __reduce_max_sync(0xffffffffu, key);
        int bestp = 31 - (int)(m & 31u);
        float best = __shfl_sync(0xffffffffu, sc, bestp);
        if (p == 0) {
            bp[t][n] = (unsigned char)bestp;
            fv[(t + 1) & 1][n] = best + feats[t * KTAG + n];   // LDS, off-chain
        }
        __syncthreads();
    }

    if (n == 0) {
        float tv = fv[TT & 1][p] + trans[STOP_TAG * KTAG + p];
        unsigned key = (fkey(tv) & ~31u) | (31u - p);
        unsigned m = __reduce_max_sync(0xffffffffu, key);
        int bidx = 31 - (int)(m & 31u);
        float bv = __shfl_sync(0xffffffffu, tv, bidx);
        if (p == 0) {
            out[0] = bv;                     // score
            out[TT] = (float)bidx;           // path[T-1] = best
            int tag = bidx;
            for (int t = TT - 1; t >= 1; t--) {
                tag = bp[t][tag];
                out[t] = (float)tag;         // path[t-1]
            }
        }
    }
}

// ---------------- launch ----------------
extern "C" void kernel_launch(void* const* d_in, const int* in_sizes, int n_in,
                              void* d_out, int out_size)
{
    const int*   sentence = (const int*)d_in[0];
    const float* embed    = (const float*)d_in[1];
    const float* w_ih_f   = (const float*)d_in[2];
    const float* w_hh_f   = (const float*)d_in[3];
    const float* b_ih_f   = (const float*)d_in[4];
    const float* b_hh_f   = (const float*)d_in[5];
    const float* w_ih_b   = (const float*)d_in[6];
    const float* w_hh_b   = (const float*)d_in[7];
    const float* b_ih_b   = (const float*)d_in[8];
    const float* b_hh_b   = (const float*)d_in[9];
    const float* h0       = (const float*)d_in[10];
    const float* c0       = (const float*)d_in[11];
    const float* w_tag    = (const float*)d_in[12];
    const float* b_tag    = (const float*)d_in[13];
    const float* trans    = (const float*)d_in[14];
    float* out = (float*)d_out;

    // GEMM prologue poisons g_hx; LSTM launches after, ordering guaranteed.
    dim3 ggrid(G4 / 128, TT / 128, 2);   // 16 x 4 x 2 = 128 blocks
    gemm_xw_kernel<<<ggrid, 256>>>(sentence, embed,
                                   w_ih_f, b_ih_f, b_hh_f,
                                   w_ih_b, b_ih_b, b_hh_b);

    lstm_kernel<<<2 * NBD, LSTM_THREADS>>>(w_hh_f, w_hh_b, h0, c0);

    tag_kernel<<<TT, 256>>>(w_tag, b_tag);

    const int vit_smem_bytes = TT * KTAG * sizeof(float);   // 64 KB dynamic
    cudaFuncSetAttribute(viterbi_kernel,
                         cudaFuncAttributeMaxDynamicSharedMemorySize,
                         vit_smem_bytes);
    viterbi_kernel<<<1, 1024, vit_smem_bytes>>>(trans, out);
}